// round 5
// baseline (speedup 1.0000x reference)
#include <cuda_runtime.h>

// Gray-Scott residual: 4 outputs/thread (z-pair x 2 adjacent x rows),
// aligned float2 loads, shared x-tap rows, no smem.
// Input: output (50,2,100,100,100) fp32. Output: f_u(48,96,96,96) ++ f_v.

#define TOUT 48
#define D 96
#define IN_T 2000000
#define IN_C 1000000
#define IN_Y 10000
#define IN_X 100
#define N_OUT (TOUT * D * D * D)       // 42467328
#define N_THREADS_TOT (N_OUT / 4)      // 10616832

__device__ __forceinline__ float2 ldg2(const float* p) {
    return __ldg((const float2*)p);
}

__global__ void __launch_bounds__(256) gs_kernel4(
    const float* __restrict__ in, float* __restrict__ out)
{
    int idx = blockIdx.x * 256 + threadIdx.x;
    if (idx >= N_THREADS_TOT) return;

    int zp = idx % (D / 2);            // z pair: outputs z = 2zp, 2zp+1
    int r  = idx / (D / 2);
    int xp = r % (D / 2);              // x pair: outputs x = 2xp, 2xp+1
    r /= (D / 2);
    int y  = r % D;
    int t  = r / D;

    const int zi = 2 * zp;
    const int xi = 2 * xp;

    // base: (t, ch, y+2, x_in=xi, z_in=zi+2)
    const float* B = in + t * IN_T + (y + 2) * IN_Y + xi * IN_X + (zi + 2);

    const float INV_DX2 = 2304.0f / 10000.0f;
    const float C1 = 4.0f / 3.0f;
    const float C2 = -1.0f / 12.0f;
    const float C0 = -7.5f;

    float lap_s[2][4];   // [ch][point]: points = (rowA,z0),(rowA,z1),(rowB,z0),(rowB,z1)
    float c_s[2][4];     // centers
    float n_s[2][4];     // t+1 centers

    #pragma unroll
    for (int ch = 0; ch < 2; ch++) {
        const float* p = B + ch * IN_C;

        // center rows (x_in = xi+2, xi+3): z-window z_in [zi..zi+5]
        const float* pa = p + 2 * IN_X;
        const float* pb = p + 3 * IN_X;
        float2 za = ldg2(pa - 2), zb = ldg2(pa), zc = ldg2(pa + 2);
        float2 zd = ldg2(pb - 2), ze = ldg2(pb), zf = ldg2(pb + 2);

        // tap-only x rows: xi, xi+1, xi+4, xi+5 (center z-pair only)
        float2 x0 = ldg2(p);
        float2 x1 = ldg2(p + IN_X);
        float2 x4 = ldg2(p + 4 * IN_X);
        float2 x5 = ldg2(p + 5 * IN_X);

        // y taps for both center rows
        float2 am2 = ldg2(pa - 2 * IN_Y), am1 = ldg2(pa - IN_Y);
        float2 ap1 = ldg2(pa + IN_Y),     ap2 = ldg2(pa + 2 * IN_Y);
        float2 bm2 = ldg2(pb - 2 * IN_Y), bm1 = ldg2(pb - IN_Y);
        float2 bp1 = ldg2(pb + IN_Y),     bp2 = ldg2(pb + 2 * IN_Y);

        // t+1 centers
        float2 na = ldg2(pa + IN_T);
        float2 nb = ldg2(pb + IN_T);

        // centers
        c_s[ch][0] = zb.x; c_s[ch][1] = zb.y;
        c_s[ch][2] = ze.x; c_s[ch][3] = ze.y;
        n_s[ch][0] = na.x; n_s[ch][1] = na.y;
        n_s[ch][2] = nb.x; n_s[ch][3] = nb.y;

        // row A (x_in = xi+2): x-1 -> x1, x+1 -> ze(row B), x-2 -> x0, x+2 -> x4
        float s1_00 = za.y + zb.y + x1.x + ze.x + am1.x + ap1.x;
        float s2_00 = za.x + zc.x + x0.x + x4.x + am2.x + ap2.x;
        float s1_01 = zb.x + zc.x + x1.y + ze.y + am1.y + ap1.y;
        float s2_01 = za.y + zc.y + x0.y + x4.y + am2.y + ap2.y;
        // row B (x_in = xi+3): x-1 -> zb(row A), x+1 -> x4, x-2 -> x1, x+2 -> x5
        float s1_10 = zd.y + ze.y + zb.x + x4.x + bm1.x + bp1.x;
        float s2_10 = zd.x + zf.x + x1.x + x5.x + bm2.x + bp2.x;
        float s1_11 = ze.x + zf.x + zb.y + x4.y + bm1.y + bp1.y;
        float s2_11 = zd.y + zf.y + x1.y + x5.y + bm2.y + bp2.y;

        lap_s[ch][0] = (C0 * c_s[ch][0] + C1 * s1_00 + C2 * s2_00) * INV_DX2;
        lap_s[ch][1] = (C0 * c_s[ch][1] + C1 * s1_01 + C2 * s2_01) * INV_DX2;
        lap_s[ch][2] = (C0 * c_s[ch][2] + C1 * s1_10 + C2 * s2_10) * INV_DX2;
        lap_s[ch][3] = (C0 * c_s[ch][3] + C1 * s1_11 + C2 * s2_11) * INV_DX2;
    }

    float2 fuA, fuB, fvA, fvB;
    float fu[4], fv[4];
    #pragma unroll
    for (int j = 0; j < 4; j++) {
        float cu = c_s[0][j], cv = c_s[1][j];
        float uv2 = cu * cv * cv;
        float u_t = (n_s[0][j] - cu) * 2.0f;   // /DT, DT=0.5
        float v_t = (n_s[1][j] - cv) * 2.0f;
        fu[j] = 0.2f * lap_s[0][j] - uv2 + 0.025f * (1.0f - cu) - u_t;
        fv[j] = 0.1f * lap_s[1][j] + uv2 - 0.08f * cv - v_t;
    }
    fuA = make_float2(fu[0], fu[1]); fuB = make_float2(fu[2], fu[3]);
    fvA = make_float2(fv[0], fv[1]); fvB = make_float2(fv[2], fv[3]);

    int oA = ((t * D + y) * D + xi) * D + zi;   // out row x = xi; row x+1 = oA + D*... 
    *(float2*)(out + oA)             = fuA;
    *(float2*)(out + oA + D)         = fuB;      // x+1 row: stride D in z-dim? NO
    *(float2*)(out + oA + N_OUT)     = fvA;
    *(float2*)(out + oA + N_OUT + D) = fvB;
}

extern "C" void kernel_launch(void* const* d_in, const int* in_sizes, int n_in,
                              void* d_out, int out_size)
{
    const float* in = (const float*)d_in[0];
    float* out = (float*)d_out;
    int blocks = (N_THREADS_TOT + 255) / 256;   // 41472
    gs_kernel4<<<blocks, 256>>>(in, out);
}